// round 16
// baseline (speedup 1.0000x reference)
#include <cuda_runtime.h>
#include <cstdint>

#define D 512
#define HW (D * D)            // 262144 = 2^18
#define NB 32                 // batch
#define IMG_ELEMS ((size_t)NB * 3 * HW)
#define LO 0.001f
#define HI 510.999f           // D - 1.001
#define NBLOCKS 8192          // 32 batch * 16 x-tiles(32 rows) * 16 y-tiles(32 cols)

__device__ __align__(16) float g_partials[NBLOCKS];

// One branch, one pixel. img points at batch-n's [3,HW] plane set.
__device__ __forceinline__ void sample_branch(const float* __restrict__ img,
                                              float qx0, float qy0, float m,
                                              float r[3],
                                              float& loss) {
    float qx = fminf(fmaxf(qx0, LO), HI);
    float qy = fminf(fmaxf(qy0, LO), HI);
    float dx = qx0 - qx;
    float dy = qy0 - qy;
    loss += dx * dx + dy * dy;

    float fx = floorf(qx);
    float fy = floorf(qy);
    float ax = qx - fx;              // in [0,1)
    float ay = qy - fy;

    int ifx = (int)fx, ify = (int)fy;
    int icx = ifx + (ax > 0.0f);     // == (int)ceilf(qx)
    int icy = ify + (ay > 0.0f);

    // weights: 1 - |q - nb|
    float wfx = 1.0f - ax;
    float wcx = 1.0f - ((float)icx - qx);
    float wfy = 1.0f - ay;
    float wcy = 1.0f - ((float)icy - qy);

    // ind = y + D * x
    int i00 = ify + (ifx << 9);
    int i10 = ify + (icx << 9);
    int i01 = icy + (ifx << 9);
    int i11 = icy + (icx << 9);

    float wff = m * (wfx * wfy);
    float wcf = m * (wcx * wfy);
    float wfc = m * (wfx * wcy);
    float wcc = m * (wcx * wcy);

#pragma unroll
    for (int c = 0; c < 3; c++) {
        const float* ic = img + (size_t)c * HW;
        r[c] += wff * __ldg(ic + i00)
              + wcf * __ldg(ic + i10)
              + wfc * __ldg(ic + i01)
              + wcc * __ldg(ic + i11);
    }
}

// Tile mapping: block = 32 rows (x) by 32 cols (y), 512 threads.
//   lane (0..31)  -> y within tile (1 cache-line column)
//   warp (0..15)  -> 2 consecutive rows (x) via ILP-2
__global__ void __launch_bounds__(512) vm_main_kernel(
    const float* __restrict__ im1,
    const float* __restrict__ im2,
    const float* __restrict__ C,
    const float* __restrict__ M1,
    const float* __restrict__ M2,
    float* __restrict__ out) {

    int bid = blockIdx.x;
    int ty = (bid & 15) << 5;            // y-tile origin (16 tiles of 32)
    int tx = ((bid >> 4) & 15) << 5;     // x-tile origin (16 tiles of 32)
    int n  = bid >> 8;                   // batch

    int lane = threadIdx.x & 31;
    int w    = threadIdx.x >> 5;

    int y  = ty + lane;                  // column, fixed per thread
    int x0 = tx + (w << 1);              // first of 2 rows

    const float* Cn  = C  + (size_t)n * 2 * HW;
    const float* M1n = M1 + (size_t)n * HW;
    const float* M2n = M2 + (size_t)n * HW;
    const float* im1n = im1 + (size_t)n * 3 * HW;
    const float* im2n = im2 + (size_t)n * 3 * HW;
    float* outn = out + (size_t)n * 3 * HW;

    float yf = (float)y;
    float loss = 0.0f;

    int p0 = (x0 << 9) + y;
    int p1 = p0 + D;

    // Front-batch all stream-once loads (evict-first) to maximize MLP.
    float c0a = __ldcs(Cn + p0);
    float c1a = __ldcs(Cn + p0 + HW);
    float m1a = __ldcs(M1n + p0);
    float m2a = __ldcs(M2n + p0);
    float c0b = __ldcs(Cn + p1);
    float c1b = __ldcs(Cn + p1 + HW);
    float m1b = __ldcs(M1n + p1);
    float m2b = __ldcs(M2n + p1);

    float xfa = (float)x0;
    float xfb = (float)(x0 + 1);

    float ra[3] = {0.0f, 0.0f, 0.0f};
    float rb[3] = {0.0f, 0.0f, 0.0f};

    // branch a: im1 sampled at q + C, masked by M1
    sample_branch(im1n, xfa + c0a, yf + c1a, m1a, ra, loss);
    // branch b: im2 sampled at q - C, masked by M2
    sample_branch(im2n, xfa - c0a, yf - c1a, m2a, ra, loss);

    sample_branch(im1n, xfb + c0b, yf + c1b, m1b, rb, loss);
    sample_branch(im2n, xfb - c0b, yf - c1b, m2b, rb, loss);

    __stcs(outn + p0,          ra[0]);
    __stcs(outn + p0 + HW,     ra[1]);
    __stcs(outn + p0 + 2 * HW, ra[2]);
    __stcs(outn + p1,          rb[0]);
    __stcs(outn + p1 + HW,     rb[1]);
    __stcs(outn + p1 + 2 * HW, rb[2]);

    // ---- loss reduction: warp shfl -> smem -> per-block partial ----
#pragma unroll
    for (int off = 16; off > 0; off >>= 1)
        loss += __shfl_down_sync(0xFFFFFFFFu, loss, off);

    __shared__ float warp_part[16];
    if (lane == 0) warp_part[w] = loss;
    __syncthreads();
    if (threadIdx.x == 0) {
        float v = warp_part[0];
#pragma unroll
        for (int k = 1; k < 16; k++) v += warp_part[k];
        g_partials[bid] = v;
    }

    // PDL: signal this block's contribution is visible; lets the dependent
    // finalize kernel's launch dependency resolve before full block retire.
#if __CUDA_ARCH__ >= 900
    cudaTriggerProgrammaticLaunchCompletion();
#endif
}

__global__ void __launch_bounds__(1024) vm_finalize_kernel(float* __restrict__ out) {
    // PDL: wait for the upstream grid before touching g_partials.
#if __CUDA_ARCH__ >= 900
    cudaGridDependencySynchronize();
#endif
    int t = threadIdx.x;
    const float4* p4 = (const float4*)g_partials;   // 2048 float4s
    float s = 0.0f;
#pragma unroll
    for (int i = 0; i < 2; i++) {
        float4 v = p4[t + i * 1024];
        s += (v.x + v.y) + (v.z + v.w);
    }
#pragma unroll
    for (int off = 16; off > 0; off >>= 1)
        s += __shfl_down_sync(0xFFFFFFFFu, s, off);
    __shared__ float warp_part[32];
    int w = t >> 5, lane = t & 31;
    if (lane == 0) warp_part[w] = s;
    __syncthreads();
    if (w == 0) {
        float v = warp_part[lane];
#pragma unroll
        for (int off = 16; off > 0; off >>= 1)
            v += __shfl_down_sync(0xFFFFFFFFu, v, off);
        if (lane == 0) {
            // la + lb = sum / (N*2*HW) / (D*D) * 0.01
            double denom = (double)NB * 2.0 * (double)HW;
            out[IMG_ELEMS] = (float)((double)v / denom * (0.01 / (double)(D * D)));
        }
    }
}

extern "C" void kernel_launch(void* const* d_in, const int* in_sizes, int n_in,
                              void* d_out, int out_size) {
    const float* im1 = (const float*)d_in[0];
    const float* im2 = (const float*)d_in[1];
    const float* C   = (const float*)d_in[2];
    const float* M1  = (const float*)d_in[3];
    const float* M2  = (const float*)d_in[4];
    float* out = (float*)d_out;

    vm_main_kernel<<<NBLOCKS, 512>>>(im1, im2, C, M1, M2, out);

    if ((size_t)out_size > IMG_ELEMS) {
        // Programmatic dependent launch: overlap finalize launch latency with
        // the main kernel's drain; device-side sync provides ordering.
        cudaLaunchConfig_t cfg = {};
        cfg.gridDim  = dim3(1, 1, 1);
        cfg.blockDim = dim3(1024, 1, 1);
        cfg.dynamicSmemBytes = 0;
        cfg.stream = 0;
        cudaLaunchAttribute attr[1];
        attr[0].id = cudaLaunchAttributeProgrammaticStreamSerialization;
        attr[0].val.programmaticStreamSerializationAllowed = 1;
        cfg.attrs = attr;
        cfg.numAttrs = 1;
        cudaError_t e = cudaLaunchKernelEx(&cfg, vm_finalize_kernel, out);
        if (e != cudaSuccess) {
            vm_finalize_kernel<<<1, 1024>>>(out);
        }
    }
}

// round 17
// speedup vs baseline: 1.0419x; 1.0419x over previous
#include <cuda_runtime.h>
#include <cstdint>

#define D 512
#define HW (D * D)            // 262144 = 2^18
#define NB 32                 // batch
#define IMG_ELEMS ((size_t)NB * 3 * HW)
#define LO 0.001f
#define HI 510.999f           // D - 1.001
#define NBLOCKS 8192          // 32 batch * 16 x-tiles(32 rows) * 16 y-tiles(32 cols)

__device__ __align__(16) float g_partials[NBLOCKS];

// One branch, one pixel. img points at batch-n's [3,HW] plane set.
__device__ __forceinline__ void sample_branch(const float* __restrict__ img,
                                              float qx0, float qy0, float m,
                                              float r[3],
                                              float& loss) {
    float qx = fminf(fmaxf(qx0, LO), HI);
    float qy = fminf(fmaxf(qy0, LO), HI);
    float dx = qx0 - qx;
    float dy = qy0 - qy;
    loss += dx * dx + dy * dy;

    float fx = floorf(qx);
    float fy = floorf(qy);
    float ax = qx - fx;              // in [0,1)
    float ay = qy - fy;

    int ifx = (int)fx, ify = (int)fy;
    int icx = ifx + (ax > 0.0f);     // == (int)ceilf(qx)
    int icy = ify + (ay > 0.0f);

    // weights: 1 - |q - nb|
    float wfx = 1.0f - ax;
    float wcx = 1.0f - ((float)icx - qx);
    float wfy = 1.0f - ay;
    float wcy = 1.0f - ((float)icy - qy);

    // ind = y + D * x
    int i00 = ify + (ifx << 9);
    int i10 = ify + (icx << 9);
    int i01 = icy + (ifx << 9);
    int i11 = icy + (icx << 9);

    float wff = m * (wfx * wfy);
    float wcf = m * (wcx * wfy);
    float wfc = m * (wfx * wcy);
    float wcc = m * (wcx * wcy);

#pragma unroll
    for (int c = 0; c < 3; c++) {
        const float* ic = img + (size_t)c * HW;
        r[c] += wff * __ldg(ic + i00)
              + wcf * __ldg(ic + i10)
              + wfc * __ldg(ic + i01)
              + wcc * __ldg(ic + i11);
    }
}

// Tile mapping: block = 32 rows (x) by 32 cols (y), 512 threads.
//   lane (0..31)  -> y within tile (1 cache-line column)
//   warp (0..15)  -> 2 consecutive rows (x) via ILP-2
__global__ void __launch_bounds__(512) vm_main_kernel(
    const float* __restrict__ im1,
    const float* __restrict__ im2,
    const float* __restrict__ C,
    const float* __restrict__ M1,
    const float* __restrict__ M2,
    float* __restrict__ out) {

    int bid = blockIdx.x;
    int ty = (bid & 15) << 5;            // y-tile origin (16 tiles of 32)
    int tx = ((bid >> 4) & 15) << 5;     // x-tile origin (16 tiles of 32)
    int n  = bid >> 8;                   // batch

    int lane = threadIdx.x & 31;
    int w    = threadIdx.x >> 5;

    int y  = ty + lane;                  // column, fixed per thread
    int x0 = tx + (w << 1);              // first of 2 rows

    const float* Cn  = C  + (size_t)n * 2 * HW;
    const float* M1n = M1 + (size_t)n * HW;
    const float* M2n = M2 + (size_t)n * HW;
    const float* im1n = im1 + (size_t)n * 3 * HW;
    const float* im2n = im2 + (size_t)n * 3 * HW;
    float* outn = out + (size_t)n * 3 * HW;

    float yf = (float)y;
    float loss = 0.0f;

    int p0 = (x0 << 9) + y;
    int p1 = p0 + D;

    // Front-batch all stream-once loads (evict-first) to maximize MLP.
    float c0a = __ldcs(Cn + p0);
    float c1a = __ldcs(Cn + p0 + HW);
    float m1a = __ldcs(M1n + p0);
    float m2a = __ldcs(M2n + p0);
    float c0b = __ldcs(Cn + p1);
    float c1b = __ldcs(Cn + p1 + HW);
    float m1b = __ldcs(M1n + p1);
    float m2b = __ldcs(M2n + p1);

    float xfa = (float)x0;
    float xfb = (float)(x0 + 1);

    float ra[3] = {0.0f, 0.0f, 0.0f};
    float rb[3] = {0.0f, 0.0f, 0.0f};

    // branch a: im1 sampled at q + C, masked by M1
    sample_branch(im1n, xfa + c0a, yf + c1a, m1a, ra, loss);
    // branch b: im2 sampled at q - C, masked by M2
    sample_branch(im2n, xfa - c0a, yf - c1a, m2a, ra, loss);

    sample_branch(im1n, xfb + c0b, yf + c1b, m1b, rb, loss);
    sample_branch(im2n, xfb - c0b, yf - c1b, m2b, rb, loss);

    __stcs(outn + p0,          ra[0]);
    __stcs(outn + p0 + HW,     ra[1]);
    __stcs(outn + p0 + 2 * HW, ra[2]);
    __stcs(outn + p1,          rb[0]);
    __stcs(outn + p1 + HW,     rb[1]);
    __stcs(outn + p1 + 2 * HW, rb[2]);

    // ---- loss reduction: warp shfl -> smem -> per-block partial ----
#pragma unroll
    for (int off = 16; off > 0; off >>= 1)
        loss += __shfl_down_sync(0xFFFFFFFFu, loss, off);

    __shared__ float warp_part[16];
    if (lane == 0) warp_part[w] = loss;
    __syncthreads();
    if (threadIdx.x == 0) {
        float v = warp_part[0];
#pragma unroll
        for (int k = 1; k < 16; k++) v += warp_part[k];
        g_partials[bid] = v;
    }
}

__global__ void __launch_bounds__(1024) vm_finalize_kernel(float* __restrict__ out) {
    // PDL: wait for the upstream grid before touching g_partials.
#if __CUDA_ARCH__ >= 900
    cudaGridDependencySynchronize();
#endif
    int t = threadIdx.x;
    const float4* p4 = (const float4*)g_partials;   // 2048 float4s
    float s = 0.0f;
#pragma unroll
    for (int i = 0; i < 2; i++) {
        float4 v = p4[t + i * 1024];
        s += (v.x + v.y) + (v.z + v.w);
    }
#pragma unroll
    for (int off = 16; off > 0; off >>= 1)
        s += __shfl_down_sync(0xFFFFFFFFu, s, off);
    __shared__ float warp_part[32];
    int w = t >> 5, lane = t & 31;
    if (lane == 0) warp_part[w] = s;
    __syncthreads();
    if (w == 0) {
        float v = warp_part[lane];
#pragma unroll
        for (int off = 16; off > 0; off >>= 1)
            v += __shfl_down_sync(0xFFFFFFFFu, v, off);
        if (lane == 0) {
            // la + lb = sum / (N*2*HW) / (D*D) * 0.01
            double denom = (double)NB * 2.0 * (double)HW;
            out[IMG_ELEMS] = (float)((double)v / denom * (0.01 / (double)(D * D)));
        }
    }
}

extern "C" void kernel_launch(void* const* d_in, const int* in_sizes, int n_in,
                              void* d_out, int out_size) {
    const float* im1 = (const float*)d_in[0];
    const float* im2 = (const float*)d_in[1];
    const float* C   = (const float*)d_in[2];
    const float* M1  = (const float*)d_in[3];
    const float* M2  = (const float*)d_in[4];
    float* out = (float*)d_out;

    vm_main_kernel<<<NBLOCKS, 512>>>(im1, im2, C, M1, M2, out);

    if ((size_t)out_size > IMG_ELEMS) {
        // Programmatic dependent launch: overlap finalize launch latency with
        // the main kernel's drain; device-side sync provides ordering.
        cudaLaunchConfig_t cfg = {};
        cfg.gridDim  = dim3(1, 1, 1);
        cfg.blockDim = dim3(1024, 1, 1);
        cfg.dynamicSmemBytes = 0;
        cfg.stream = 0;
        cudaLaunchAttribute attr[1];
        attr[0].id = cudaLaunchAttributeProgrammaticStreamSerialization;
        attr[0].val.programmaticStreamSerializationAllowed = 1;
        cfg.attrs = attr;
        cfg.numAttrs = 1;
        cudaError_t e = cudaLaunchKernelEx(&cfg, vm_finalize_kernel, out);
        if (e != cudaSuccess) {
            vm_finalize_kernel<<<1, 1024>>>(out);
        }
    }
}